// round 17
// baseline (speedup 1.0000x reference)
#include <cuda_runtime.h>
#include <cuda_fp16.h>

#define HWSZ 262144           // 512*512
#define NB 8
#define FDIM 257              // live quadrant: x0,y0 in [255,511]
#define FOFF (255 * FDIM + 255)
#define FSZ (FDIM * FDIM)

// 5 scalar sample fields f_k = dot(w2_k, img), quad-packed, quadrant only.
// Layout [b][k] so per-k offsets fold into LDG immediates.
__device__ uint2 g_f[NB * 5 * FSZ];
// Conv outputs: z[8] per pixel, fp32 (coords need fp32 precision). 67 MB.
__device__ float g_z[NB * HWSZ * 8];

// ---------------------------------------------------------------------------
__device__ __forceinline__ unsigned long long pk2(float lo, float hi) {
    unsigned long long r;
    asm("mov.b64 %0, {%1, %2};" : "=l"(r) : "f"(lo), "f"(hi));
    return r;
}
__device__ __forceinline__ void upk2(float& lo, float& hi, unsigned long long v) {
    asm("mov.b64 {%0, %1}, %2;" : "=f"(lo), "=f"(hi) : "l"(v));
}
__device__ __forceinline__ unsigned long long fma2(unsigned long long a,
                                                   unsigned long long b,
                                                   unsigned long long c) {
    unsigned long long d;
    asm("fma.rn.f32x2 %0, %1, %2, %3;" : "=l"(d) : "l"(a), "l"(b), "l"(c));
    return d;
}

// ---------------------------------------------------------------------------
// Kernel 1: build the quadrant fields. grid (9,9,8), block (32,8).
// ---------------------------------------------------------------------------
__global__ __launch_bounds__(256) void k_prep(const float* __restrict__ x,
                                              const float* __restrict__ w2) {
    __shared__ float4 tile[33][33];
    __shared__ float4 s_w2[5];
    int b  = blockIdx.z;
    int h0 = 255 + (blockIdx.y << 5);
    int w0 = 255 + (blockIdx.x << 5);
    int tx = threadIdx.x, ty = threadIdx.y;
    int t = (ty << 5) + tx;
    if (t < 5) s_w2[t] = make_float4(w2[3 * t], w2[3 * t + 1], w2[3 * t + 2], 0.f);

    const float* xb = x + (size_t)b * 3 * HWSZ;
#pragma unroll
    for (int r = 0; r < 5; r++) {
        int rr = ty + (r << 3);
        if (rr < 33) {
            int hh = h0 + rr;
#pragma unroll
            for (int jj = 0; jj < 2; jj++) {
                int j = tx + (jj << 5);
                if (j < 33) {
                    int ww = w0 + j;
                    float4 v = make_float4(0.f, 0.f, 0.f, 0.f);
                    if (hh < 512 && ww < 512) {
                        int hw = (hh << 9) + ww;
                        v = make_float4(xb[hw], xb[HWSZ + hw], xb[2 * HWSZ + hw], 0.f);
                    }
                    tile[rr][j] = v;
                }
            }
        }
    }
    __syncthreads();

    int fy = h0 + tx - 255;
    if (fy >= FDIM) return;
#pragma unroll
    for (int r = 0; r < 4; r++) {
        int cc = ty + (r << 3);
        int fx = w0 + cc - 255;
        if (fx >= FDIM) continue;
        float4 v00 = tile[tx][cc];
        float4 v01 = tile[tx + 1][cc];
        float4 v10 = tile[tx][cc + 1];
        float4 v11 = tile[tx + 1][cc + 1];
        int base = fx * FDIM + fy;
#pragma unroll
        for (int k = 0; k < 5; k++) {
            float4 wv = s_w2[k];
            float f00 = v00.x * wv.x + v00.y * wv.y + v00.z * wv.z;
            float f01 = v01.x * wv.x + v01.y * wv.y + v01.z * wv.z;
            float f10 = v10.x * wv.x + v10.y * wv.y + v10.z * wv.z;
            float f11 = v11.x * wv.x + v11.y * wv.y + v11.z * wv.z;
            __half2 pa = __floats2half2_rn(f00, f01);
            __half2 pb = __floats2half2_rn(f10, f11);
            uint2 q;
            q.x = *reinterpret_cast<unsigned*>(&pa);
            q.y = *reinterpret_cast<unsigned*>(&pb);
            g_f[(b * 5 + k) * FSZ + base] = q;
        }
    }
}

// ---------------------------------------------------------------------------
// Kernel A: conv3x3 only (smem tile; f32x2 over output-channel pairs).
// Streams z[8] per pixel to g_z, fully coalesced.
// Block 128 = 256 px of one row (2 px/thread). grid (2, 512, 8).
// ---------------------------------------------------------------------------
__global__ __launch_bounds__(128) void k_conv(const float* __restrict__ x,
                                              const float* __restrict__ w1,
                                              const float* __restrict__ b1) {
    __shared__ float s_tile[3][3][264];            // [row][ch][col j], j -> w0-1+j
    __shared__ unsigned long long s_w1q[27][4];    // [tap][p] = (w1[2p][tap], w1[2p+1][tap])
    __shared__ unsigned long long s_b1q[4];

    int t = threadIdx.x;
    int w0 = blockIdx.x << 8;
    int h  = blockIdx.y;
    int b  = blockIdx.z;

    if (t < 108) {
        int p = t & 3, tap = t >> 2;
        s_w1q[tap][p] = pk2(w1[(2 * p) * 27 + tap], w1[(2 * p + 1) * 27 + tap]);
    } else if (t < 112) {
        int p = t - 108;
        s_b1q[p] = pk2(b1[2 * p], b1[2 * p + 1]);
    }

    // ---- cooperative tile load: rows h-1..h+1, 3 channels, cols w0-1..w0+256 ----
    const float* xb = x + (size_t)b * 3 * HWSZ;
#pragma unroll
    for (int rw = 0; rw < 3; rw++) {
        int hh = h + rw - 1;
        bool vh = ((unsigned)hh < 512u);
#pragma unroll
        for (int ch = 0; ch < 3; ch++) {
            const float* src = xb + (ch << 18) + (hh << 9);
#pragma unroll
            for (int jj = 0; jj < 3; jj++) {
                int j = t + (jj << 7);
                if (j < 258) {
                    int wg = w0 - 1 + j;
                    float v = (vh && (unsigned)wg < 512u) ? __ldg(src + wg) : 0.f;
                    s_tile[rw][ch][j] = v;
                }
            }
        }
    }
    __syncthreads();

    // ---- conv3x3: o-pair packed f32x2 ----
    unsigned long long zzA[4], zzB[4];
#pragma unroll
    for (int p = 0; p < 4; p++) { zzA[p] = s_b1q[p]; zzB[p] = s_b1q[p]; }

#pragma unroll
    for (int rw = 0; rw < 3; rw++) {
#pragma unroll
        for (int ch = 0; ch < 3; ch++) {
            float2 a = *reinterpret_cast<const float2*>(&s_tile[rw][ch][2 * t]);
            float2 c = *reinterpret_cast<const float2*>(&s_tile[rw][ch][2 * t + 2]);
            unsigned long long d0 = pk2(a.x, a.x);
            unsigned long long d1 = pk2(a.y, a.y);
            unsigned long long d2 = pk2(c.x, c.x);
            unsigned long long d3 = pk2(c.y, c.y);
            int tap = ch * 9 + rw * 3;
#pragma unroll
            for (int dj = 0; dj < 3; dj++) {
                ulonglong2 wa = *reinterpret_cast<const ulonglong2*>(&s_w1q[tap + dj][0]);
                ulonglong2 wb = *reinterpret_cast<const ulonglong2*>(&s_w1q[tap + dj][2]);
                unsigned long long pA = dj == 0 ? d0 : (dj == 1 ? d1 : d2);
                unsigned long long pB = dj == 0 ? d1 : (dj == 1 ? d2 : d3);
                zzA[0] = fma2(pA, wa.x, zzA[0]);
                zzA[1] = fma2(pA, wa.y, zzA[1]);
                zzA[2] = fma2(pA, wb.x, zzA[2]);
                zzA[3] = fma2(pA, wb.y, zzA[3]);
                zzB[0] = fma2(pB, wa.x, zzB[0]);
                zzB[1] = fma2(pB, wa.y, zzB[1]);
                zzB[2] = fma2(pB, wb.x, zzB[2]);
                zzB[3] = fma2(pB, wb.y, zzB[3]);
            }
        }
    }

    float z0[8], z1[8];
#pragma unroll
    for (int p = 0; p < 4; p++) {
        upk2(z0[2 * p], z0[2 * p + 1], zzA[p]);
        upk2(z1[2 * p], z1[2 * p + 1], zzB[p]);
    }

    // ---- stream z to g_z: 64B contiguous per thread, coalesced ----
    int po = (b << 18) + (h << 9) + w0 + (t << 1);
    float4* zp = reinterpret_cast<float4*>(g_z + (size_t)po * 8);
    zp[0] = make_float4(z0[0], z0[1], z0[2], z0[3]);
    zp[1] = make_float4(z0[4], z0[5], z0[6], z0[7]);
    zp[2] = make_float4(z1[0], z1[1], z1[2], z1[3]);
    zp[3] = make_float4(z1[4], z1[5], z1[6], z1[7]);
}

// ---------------------------------------------------------------------------
// Bilinear sample of a quadrant field (branchy early-out, R8-proven):
// ONE scattered 8B load + 6 flops.
// ---------------------------------------------------------------------------
__device__ __forceinline__ void samp(const uint2* __restrict__ fld,
                                     float gx, float gy, float& acc) {
    float ix = fmaf(gx, 256.f, 255.5f);
    float iy = fmaf(gy, 256.f, 255.5f);
    if (ix >= 512.f || iy >= 512.f) return;
    int x0 = (int)ix, y0 = (int)iy;
    float wx1 = ix - (float)x0, wy1 = iy - (float)y0;
    uint2 q = __ldg(fld + (x0 * FDIM + y0 - FOFF));
    float2 fa = __half22float2(*reinterpret_cast<__half2*>(&q.x));
    float2 fb = __half22float2(*reinterpret_cast<__half2*>(&q.y));
    float ca = fa.x + wy1 * (fa.y - fa.x);
    float cb = fb.x + wy1 * (fb.y - fb.x);
    acc += ca + wx1 * (cb - ca);
}
__device__ __forceinline__ void samp_c(const uint2* __restrict__ fld,
                                       float gx, float gy, float& acc) {
    float ix = fmaf(gx, 256.f, 255.5f);
    float iy = fmaf(gy, 256.f, 255.5f);
    int x0 = (int)ix, y0 = (int)iy;
    float wx1 = ix - (float)x0, wy1 = iy - (float)y0;
    uint2 q = __ldg(fld + (x0 * FDIM + y0 - FOFF));
    float2 fa = __half22float2(*reinterpret_cast<__half2*>(&q.x));
    float2 fb = __half22float2(*reinterpret_cast<__half2*>(&q.y));
    float ca = fa.x + wy1 * (fa.y - fa.x);
    float cb = fb.x + wy1 * (fb.y - fb.x);
    acc += ca + wx1 * (cb - ca);
}

// ---------------------------------------------------------------------------
// Kernel B: sampling. 1 px/thread, 256-thr blocks, grid 8192.
// Load z[8], sigmoid, 5 field samples, store 3 channels.
// ch2 = relu(b2[2]) constant; ch1 = k3 + center.
// ---------------------------------------------------------------------------
__global__ __launch_bounds__(256) void k_samp(const float* __restrict__ b2,
                                              float* __restrict__ out) {
    int p = blockIdx.x * 256 + threadIdx.x;       // global pixel index
    int b  = p >> 18;
    int hw = p & (HWSZ - 1);
    int h  = hw >> 9;
    int w  = hw & 511;

    const float4* zp = reinterpret_cast<const float4*>(g_z + (size_t)p * 8);
    float4 za = __ldg(zp);
    float4 zb = __ldg(zp + 1);

    float s[8];
    s[0] = __fdividef(1.f, 1.f + __expf(-za.x));
    s[1] = __fdividef(1.f, 1.f + __expf(-za.y));
    s[2] = __fdividef(1.f, 1.f + __expf(-za.z));
    s[3] = __fdividef(1.f, 1.f + __expf(-za.w));
    s[4] = __fdividef(1.f, 1.f + __expf(-zb.x));
    s[5] = __fdividef(1.f, 1.f + __expf(-zb.y));
    s[6] = __fdividef(1.f, 1.f + __expf(-zb.z));
    s[7] = __fdividef(1.f, 1.f + __expf(-zb.w));

    const uint2* fbase = g_f + b * 5 * FSZ;
    float hb = (float)h * (1.f / 511.f);
    float wb = (float)w * (1.f / 511.f);

    float a0 = 0.f, a1 = 0.f;
    samp(fbase + 0 * FSZ, hb + s[0], wb + s[1], a0);   // k=0
    samp(fbase + 1 * FSZ, hb + s[2], wb + s[3], a0);   // k=1
    samp(fbase + 2 * FSZ, hb + s[4], wb + s[5], a0);   // k=2
    samp(fbase + 3 * FSZ, hb + s[6], wb + s[7], a1);   // k=3
    samp_c(fbase + 4 * FSZ, hb,      wb,        a1);   // k=4 center

    float vb0 = __ldg(b2), vb1 = __ldg(b2 + 1), vb2 = __ldg(b2 + 2);
    int po = b * 3 * HWSZ + hw;
    out[po]            = fmaxf(a0 + vb0, 0.f);
    out[po + HWSZ]     = fmaxf(a1 + vb1, 0.f);
    out[po + 2 * HWSZ] = fmaxf(vb2, 0.f);
}

// ---------------------------------------------------------------------------
extern "C" void kernel_launch(void* const* d_in, const int* in_sizes, int n_in,
                              void* d_out, int out_size) {
    const float* x  = (const float*)d_in[0];
    const float* w1 = (const float*)d_in[1];
    const float* b1 = (const float*)d_in[2];
    const float* w2 = (const float*)d_in[3];
    const float* b2 = (const float*)d_in[4];
    float* out = (float*)d_out;

    k_prep<<<dim3(9, 9, NB), dim3(32, 8)>>>(x, w2);
    k_conv<<<dim3(2, 512, NB), 128>>>(x, w1, b1);
    k_samp<<<NB * HWSZ / 256, 256>>>(b2, out);
}